// round 11
// baseline (speedup 1.0000x reference)
#include <cuda_runtime.h>
#include <math.h>

#define NV 1024
#define NB 16
#define GRID_DIM 16                 // 16x16 cells of 25m over [0,400)
#define NCELL (GRID_DIM * GRID_DIM)
#define WPB 8                       // warps (=egos) per block
#define BTHREADS (WPB * 32)         // 256

// Original-order data
__device__ float2 g_pos[NB * NV];         // {x, y}
__device__ float4 g_att[NB * NV];         // {cos, sin, v, 0}
// Cell-sorted per-batch data
__device__ float2 g_spos[NB * NV];
__device__ float4 g_satt[NB * NV];
__device__ int    g_cstart[NB * (NCELL + 1)];

// One block per batch: sincos + counting-sort into the 16x16 grid.
__global__ __launch_bounds__(512) void prep_kernel(const float* __restrict__ state)
{
    __shared__ int counts[NCELL];
    __shared__ int scan[NCELL];
    __shared__ int offs[NCELL];

    const int bat = blockIdx.x;
    const int t = threadIdx.x;
    const int base = bat * NV;
    const float* st = state + (size_t)bat * NV * 5;

    if (t < NCELL) counts[t] = 0;
    __syncthreads();

    float x[2], y[2], v[2], c[2], s[2];
    int cl[2];
    #pragma unroll
    for (int q = 0; q < 2; q++) {
        int i = t + q * 512;
        const float* p = st + i * 5;
        x[q] = p[0]; y[q] = p[1]; v[q] = p[2];
        float psi = p[3];
        sincosf(psi, &s[q], &c[q]);
        int cx = max(0, min(GRID_DIM - 1, (int)(x[q] * 0.04f)));
        int cy = max(0, min(GRID_DIM - 1, (int)(y[q] * 0.04f)));
        cl[q] = cy * GRID_DIM + cx;
        atomicAdd(&counts[cl[q]], 1);
        g_pos[base + i] = make_float2(x[q], y[q]);
        g_att[base + i] = make_float4(c[q], s[q], v[q], 0.0f);
    }
    __syncthreads();

    if (t < NCELL) scan[t] = counts[t];
    __syncthreads();
    for (int d = 1; d < NCELL; d <<= 1) {
        int val = 0;
        if (t < NCELL && t >= d) val = scan[t - d];
        __syncthreads();
        if (t < NCELL) scan[t] += val;
        __syncthreads();
    }
    if (t < NCELL) {
        int e = scan[t] - counts[t];               // exclusive
        offs[t] = e;
        g_cstart[bat * (NCELL + 1) + t] = e;
    }
    if (t == 0) g_cstart[bat * (NCELL + 1) + NCELL] = NV;
    __syncthreads();

    #pragma unroll
    for (int q = 0; q < 2; q++) {
        int p = atomicAdd(&offs[cl[q]], 1);
        g_spos[base + p] = make_float2(x[q], y[q]);
        g_satt[base + p] = make_float4(c[q], s[q], v[q], 0.0f);
    }
}

// One warp per ego, NO shared memory, NO barriers — all data via L2
// (working set 24KB/batch, 384KB total, fully L2-resident).
// 5x5-cell neighborhood covers the stop check (dr<20 => 3x3) and, with
// ~0.99 probability, the leader: outside the 5x5, dr>=50 so nd>=46.98.
__global__ __launch_bounds__(BTHREADS)
void rulepolicy_kernel(const float* __restrict__ lengths,
                       const float* __restrict__ v0p,
                       const float* __restrict__ s0p,
                       const float* __restrict__ dthp,
                       const float* __restrict__ amaxp,
                       const float* __restrict__ bp,
                       float* __restrict__ out)
{
    const int lane = threadIdx.x & 31;
    const int w = threadIdx.x >> 5;
    const int bat = blockIdx.y;
    const int base = bat * NV;
    const int jl = blockIdx.x * WPB + w;           // ego original index

    const float4 att = __ldg(&g_att[base + jl]);
    const float cj = att.x, sj = att.y, vj = att.z;
    const float2 ep = __ldg(&g_pos[base + jl]);
    const float xj = ep.x, yj = ep.y;

    const float C20SQ = 0.8830222215594891f;   // cos^2(20deg)
    const float C45   = 0.7071067811865476f;   // cos(45deg)
    const float INF   = __int_as_float(0x7f800000);
    const float TERM  = 46.9f;                 // < 50*cos20 = 46.984 (safe margin)

    const int* cs = g_cstart + bat * (NCELL + 1);
    const float2* sp = g_spos + base;
    const float4* sa = g_satt + base;

    float best = INF;
    int   bidx = 0;
    int   stopi = 0;

    // ── 5x5 neighborhood: leader + stop in one pass ──
    {
        int cx = max(0, min(GRID_DIM - 1, (int)(xj * 0.04f)));
        int cy = max(0, min(GRID_DIM - 1, (int)(yj * 0.04f)));
        int x0 = max(cx - 2, 0), x1 = min(cx + 2, GRID_DIM - 1);
        int y0 = max(cy - 2, 0), y1 = min(cy + 2, GRID_DIM - 1);
        for (int ry = y0; ry <= y1; ry++) {
            int beg = __ldg(&cs[ry * GRID_DIM + x0]);
            int end = __ldg(&cs[ry * GRID_DIM + x1 + 1]);
            for (int i = beg + lane; i < end; i += 32) {
                float2 p = __ldg(&sp[i]);
                float4 a = __ldg(&sa[i]);
                float dx = p.x - xj, dy = p.y - yj;
                float r2 = fmaf(dx, dx, dy * dy);
                float nd = fmaf(dx, cj, dy * sj);          // dr*cos(delpsi)
                float m  = fminf(nd, fmaf(-C20SQ, r2, nd * nd));
                float e  = (m > 0.0f) ? nd : INF;
                bool  c  = e < best;
                best = c ? e : best;  bidx = c ? i : bidx;
                float cpd = fmaf(a.x, cj, a.y * sj);       // cos(psi_i-psi_j)
                stopi |= (int)((r2 < 400.0f) & (nd > 0.0f)
                               & (nd * nd > 0.25f * r2)
                               & (cpd < C45) & (a.z > vj));
            }
        }
    }

    // ── Warp reduce (min + index tiebreak + OR); result uniform across lanes ──
    #pragma unroll
    for (int m = 1; m <= 16; m <<= 1) {
        float ob = __shfl_xor_sync(0xFFFFFFFFu, best, m);
        int   oi = __shfl_xor_sync(0xFFFFFFFFu, bidx, m);
        int   os = __shfl_xor_sync(0xFFFFFFFFu, stopi, m);
        if (ob < best || (ob == best && oi < bidx)) { best = ob; bidx = oi; }
        stopi |= os;
    }

    // ── Rare fallback: neighborhood couldn't certify the leader ──
    if (best >= TERM) {
        for (int i = lane; i < NV; i += 32) {
            float2 p = __ldg(&sp[i]);
            float dx = p.x - xj, dy = p.y - yj;
            float r2 = fmaf(dx, dx, dy * dy);
            float nd = fmaf(dx, cj, dy * sj);
            float m  = fminf(nd, fmaf(-C20SQ, r2, nd * nd));
            float e  = (m > 0.0f) ? nd : INF;
            bool  c  = e < best;
            best = c ? e : best;  bidx = c ? i : bidx;
        }
        #pragma unroll
        for (int m = 1; m <= 16; m <<= 1) {
            float ob = __shfl_xor_sync(0xFFFFFFFFu, best, m);
            int   oi = __shfl_xor_sync(0xFFFFFFFFu, bidx, m);
            if (ob < best || (ob == best && oi < bidx)) { best = ob; bidx = oi; }
        }
    }

    if (lane == 0) {
        const float V0 = __ldg(&v0p[0]), S0 = __ldg(&s0p[0]), DTH = __ldg(&dthp[0]);
        const float AMAX = __ldg(&amaxp[0]), BB = __ldg(&bp[0]);

        float4 ld = __ldg(&sa[bidx]);           // leader {cos, sin, v} (sorted idx)
        float dvx = ld.z * ld.x - vj * cj;
        float dvy = ld.z * ld.y - vj * sj;
        float ndv = fmaf(dvx, cj, dvy * sj);    // dv*cos(vdelpsi), exact incl. dv=0

        float sal   = best - __ldg(&lengths[jl]);
        float sstar = S0 + vj * DTH + (vj * ndv) / (2.0f * sqrtf(AMAX * BB));
        float q  = vj / V0;
        float q2 = q * q;
        float afree = AMAX * (1.0f - q2 * q2);

        float action;
        if (stopi) {
            action = afree - AMAX;              // ratio = 1
        } else if (isinf(sal) || isnan(sal)) {
            action = afree;
        } else {
            float r = sstar / sal;
            action = afree - AMAX * r * r;
        }
        out[bat * NV + jl] = action;
    }
}

extern "C" void kernel_launch(void* const* d_in, const int* in_sizes, int n_in,
                              void* d_out, int out_size)
{
    const float* state   = (const float*)d_in[0];
    const float* lengths = (const float*)d_in[1];
    const float* v0      = (const float*)d_in[2];
    const float* s0      = (const float*)d_in[3];
    const float* dth     = (const float*)d_in[4];
    const float* amax    = (const float*)d_in[5];
    const float* b       = (const float*)d_in[6];
    float* out = (float*)d_out;

    prep_kernel<<<NB, 512>>>(state);
    dim3 grid(NV / WPB, NB);
    rulepolicy_kernel<<<grid, BTHREADS>>>(lengths, v0, s0, dth, amax, b, out);
}